// round 11
// baseline (speedup 1.0000x reference)
#include <cuda_runtime.h>
#include <cuda_bf16.h>
#include <stdint.h>

#define BATCH   8192
#define IN_DIM  2048
#define OUT_DIM 2048
#define DEPTH   5

// ---------------- device scratch (no allocs allowed) ----------------
__device__ __nv_bfloat16 g_A2[(size_t)2 * BATCH * IN_DIM];    // rows 0..8191 = hi(x), 8192.. = lo(x)
__device__ __nv_bfloat16 g_W2[(size_t)2 * OUT_DIM * IN_DIM];  // rows n = hi(W^T), 2048+n = lo(W^T)
__device__ float g_add[OUT_DIM];                              // bias + hd

// ---------------- PTX helpers (family-stable only) ----------------
__device__ __forceinline__ uint32_t smem_u32(const void* p) {
    uint32_t a;
    asm("{ .reg .u64 t; cvta.to.shared.u64 t, %1; cvt.u32.u64 %0, t; }" : "=r"(a) : "l"(p));
    return a;
}
__device__ __forceinline__ void cpa16(uint32_t s, const void* g) {
    asm volatile("cp.async.cg.shared.global [%0], [%1], 16;" :: "r"(s), "l"(g));
}
__device__ __forceinline__ void ldm4(uint32_t* r, uint32_t addr) {
    asm volatile("ldmatrix.sync.aligned.m8n8.x4.shared.b16 {%0,%1,%2,%3}, [%4];"
                 : "=r"(r[0]), "=r"(r[1]), "=r"(r[2]), "=r"(r[3]) : "r"(addr));
}
__device__ __forceinline__ void mma_bf16(float* c, const uint32_t* a, uint32_t b0, uint32_t b1) {
    asm volatile(
        "mma.sync.aligned.m16n8k16.row.col.f32.bf16.bf16.f32 "
        "{%0,%1,%2,%3}, {%4,%5,%6,%7}, {%8,%9}, {%0,%1,%2,%3};"
        : "+f"(c[0]), "+f"(c[1]), "+f"(c[2]), "+f"(c[3])
        : "r"(a[0]), "r"(a[1]), "r"(a[2]), "r"(a[3]), "r"(b0), "r"(b1));
}
__device__ __forceinline__ float tanh_apx(float x) {
    float y;
    asm("tanh.approx.f32 %0, %1;" : "=f"(y) : "f"(x));
    return y;
}
#define SWZ(o) ((o) ^ (((o) >> 3) & 0x70))

// ---------------- prepass kernels ----------------
__global__ void conv_a_kernel(const float* __restrict__ x) {
    size_t i = (size_t)blockIdx.x * blockDim.x + threadIdx.x;  // over 4.19M float4
    float4 v = ((const float4*)x)[i];
    __nv_bfloat16 h0 = __float2bfloat16(v.x), h1 = __float2bfloat16(v.y);
    __nv_bfloat16 h2 = __float2bfloat16(v.z), h3 = __float2bfloat16(v.w);
    __nv_bfloat16 l0 = __float2bfloat16(v.x - __bfloat162float(h0));
    __nv_bfloat16 l1 = __float2bfloat16(v.y - __bfloat162float(h1));
    __nv_bfloat16 l2 = __float2bfloat16(v.z - __bfloat162float(h2));
    __nv_bfloat16 l3 = __float2bfloat16(v.w - __bfloat162float(h3));
    __nv_bfloat162* Ah = (__nv_bfloat162*)g_A2;
    __nv_bfloat162* Al = (__nv_bfloat162*)(g_A2 + (size_t)BATCH * IN_DIM);
    __nv_bfloat162 p;
    p.x = h0; p.y = h1; Ah[i * 2 + 0] = p;
    p.x = h2; p.y = h3; Ah[i * 2 + 1] = p;
    p.x = l0; p.y = l1; Al[i * 2 + 0] = p;
    p.x = l2; p.y = l3; Al[i * 2 + 1] = p;
}

__global__ void conv_w_kernel(const float* __restrict__ W) {  // W:[IN_DIM][OUT_DIM] -> W^T hi/lo
    __shared__ float t[32][33];
    int bx = blockIdx.x * 32, by = blockIdx.y * 32;
    int tx = threadIdx.x, ty = threadIdx.y;
#pragma unroll
    for (int j = 0; j < 32; j += 8)
        t[ty + j][tx] = W[(size_t)(by + ty + j) * OUT_DIM + bx + tx];
    __syncthreads();
#pragma unroll
    for (int j = 0; j < 32; j += 8) {
        float v = t[tx][ty + j];                 // = W[by+tx][bx+ty+j]
        size_t n = bx + ty + j, k = by + tx;
        __nv_bfloat16 h = __float2bfloat16(v);
        __nv_bfloat16 l = __float2bfloat16(v - __bfloat162float(h));
        g_W2[n * IN_DIM + k] = h;
        g_W2[(OUT_DIM + n) * IN_DIM + k] = l;
    }
}

__global__ void hd_bias_kernel(const float* __restrict__ hdw, const float* __restrict__ bias) {
    int o = blockIdx.x * blockDim.x + threadIdx.x;
    if (o < OUT_DIM) {
        float p = 1.0f;
#pragma unroll
        for (int d = 0; d < DEPTH; ++d)
            p *= cosf(hdw[(size_t)d * IN_DIM * OUT_DIM + (size_t)o * OUT_DIM]);
        g_add[o] = bias[o] + p * p * (1.0f / (float)IN_DIM);
    }
}

// ---------------- mma.sync GEMM ----------------
// CTA tile M=128 x N=128, K-chunk=64, K'=6144 -> 96 chunks. 8 warps (2m x 4n),
// warp tile 64x32, acc = 64 fp32 regs -> ~113 regs/thread -> 2 CTAs/SM
// (16 warps). Cross-CTA warp interleaving hides LDSM/HMMA alternation, syncs
// and cp.async bursts. 3-stage cp.async pipeline (96 KB/CTA, 192 KB/SM).
#define A_BYTES  (128 * 128)                     // 16 KB
#define B_BYTES  (128 * 128)                     // 16 KB
#define STG_B    (A_BYTES + B_BYTES)             // 32 KB
#define NCHUNK   96
#define NSTAGE   3

__device__ __forceinline__ void load_chunk(int c, uint32_t sb, int tid, int m0, int n0) {
    int seg = c >> 5;                    // 0: hi*hi, 1: hi*lo, 2: lo*hi
    int kb  = (c & 31) << 6;
    size_t arow = (seg == 2 ? (size_t)BATCH : 0) + m0;
    size_t brow = (seg == 1 ? (size_t)OUT_DIM : 0) + n0;
    const __nv_bfloat16* Ag = g_A2 + arow * IN_DIM + kb;
    const __nv_bfloat16* Bg = g_W2 + brow * IN_DIM + kb;
#pragma unroll
    for (int t = 0; t < 8; ++t) {
        int idx = tid + t * 256;
        if (idx < 1024) {                               // A: 1024 x 16B
            int r = idx >> 3, c16 = idx & 7;
            cpa16(sb + SWZ(r * 128 + c16 * 16), Ag + (size_t)r * IN_DIM + c16 * 8);
        } else {                                        // B: 1024 x 16B
            int j = idx - 1024;
            int r = j >> 3, c16 = j & 7;
            cpa16(sb + A_BYTES + SWZ(r * 128 + c16 * 16), Bg + (size_t)r * IN_DIM + c16 * 8);
        }
    }
}

__global__ __launch_bounds__(256, 2) void gemm_mma_kernel(float* __restrict__ C) {
    extern __shared__ char smem_raw[];
    const uint32_t s0 = smem_u32(smem_raw);            // dynamic smem is 1024-aligned
    const int tid = threadIdx.x;
    const int wid = tid >> 5, lane = tid & 31;
    const int warp_m = wid & 1, warp_n = wid >> 1;     // 2m x 4n
    const int m0 = blockIdx.y * 128;
    const int n0 = blockIdx.x * 128;

    // XOR-folded ldmatrix addressing: swizzle xor depends only on lane&7,
    // row-tile steps are +2048 B constants folded into LDSM immediates.
    const int lrow = lane & 7;
    const int lt = lane >> 3;
    const uint32_t xo = (uint32_t)(lrow * 16);
    const int ra0 = warp_m * 64 + (lt & 1) * 8 + lrow;   // A rows, 4 tiles of 16
    const int rb0 = warp_n * 32 + (lt & 1) * 8 + lrow;   // B rows, 2 tiles of 16
    const uint32_t a_pre0 = (uint32_t)(ra0 * 128) | xo;
    const uint32_t b_pre0 = (uint32_t)(rb0 * 128) | xo;
    const uint32_t kbase = (lt >> 1) * 16;               // 16B half-select within k16

    float acc[4][4][4];                                  // [m16 tile][n8 tile][frag]
#pragma unroll
    for (int i = 0; i < 4; ++i)
#pragma unroll
        for (int j = 0; j < 4; ++j)
#pragma unroll
            for (int q = 0; q < 4; ++q) acc[i][j][q] = 0.0f;

    // prologue: fill first 2 of 3 stages
#pragma unroll
    for (int s = 0; s < NSTAGE - 1; ++s) {
        load_chunk(s, s0 + s * STG_B, tid, m0, n0);
        asm volatile("cp.async.commit_group;" ::: "memory");
    }

    int buf = 0;
    for (int c = 0; c < NCHUNK; ++c) {
        asm volatile("cp.async.wait_group %0;" :: "n"(NSTAGE - 2) : "memory");
        __syncthreads();

        // loads for chunk c+2 into buffer of c-1 (all warps finished it before the sync)
        if (c + NSTAGE - 1 < NCHUNK) {
            int nb = buf + 2; if (nb >= NSTAGE) nb -= NSTAGE;
            load_chunk(c + NSTAGE - 1, s0 + nb * STG_B, tid, m0, n0);
        }
        asm volatile("cp.async.commit_group;" ::: "memory");

        const uint32_t Asb = s0 + buf * STG_B;
        const uint32_t Bsb = Asb + A_BYTES;
#pragma unroll
        for (int ks = 0; ks < 4; ++ks) {
            const uint32_t kof = ks * 32 + kbase;
            const uint32_t ax = Asb + (a_pre0 ^ kof);
            const uint32_t bx = Bsb + (b_pre0 ^ kof);
            uint32_t af[4][4], bf[2][4];
            ldm4(af[0], ax);
            ldm4(af[1], ax + 2048);
            ldm4(af[2], ax + 4096);
            ldm4(af[3], ax + 6144);
            ldm4(bf[0], bx);
            ldm4(bf[1], bx + 2048);
#pragma unroll
            for (int mt = 0; mt < 4; ++mt)
#pragma unroll
                for (int j = 0; j < 2; ++j) {
                    mma_bf16(acc[mt][2 * j + 0], af[mt], bf[j][0], bf[j][2]);
                    mma_bf16(acc[mt][2 * j + 1], af[mt], bf[j][1], bf[j][3]);
                }
        }
        if (++buf == NSTAGE) buf = 0;
    }

    // ---- epilogue: out = tanh(acc + bias + hd), direct fragment stores ----
    const int g = lane >> 2, tig = lane & 3;
#pragma unroll
    for (int mt = 0; mt < 4; ++mt) {
        const int r0 = m0 + warp_m * 64 + mt * 16 + g;
#pragma unroll
        for (int nt = 0; nt < 4; ++nt) {
            const int col = n0 + warp_n * 32 + nt * 8 + tig * 2;
            const float a0 = __ldg(&g_add[col]);
            const float a1 = __ldg(&g_add[col + 1]);
            float2 o0, o1;
            o0.x = tanh_apx(acc[mt][nt][0] + a0);
            o0.y = tanh_apx(acc[mt][nt][1] + a1);
            o1.x = tanh_apx(acc[mt][nt][2] + a0);
            o1.y = tanh_apx(acc[mt][nt][3] + a1);
            *(float2*)(C + (size_t)r0 * OUT_DIM + col) = o0;
            *(float2*)(C + (size_t)(r0 + 8) * OUT_DIM + col) = o1;
        }
    }
}

// ---------------- launch ----------------
#define GEMM_SMEM (NSTAGE * STG_B)   // 96 KB per CTA, 2 CTAs/SM

extern "C" void kernel_launch(void* const* d_in, const int* in_sizes, int n_in,
                              void* d_out, int out_size) {
    const float* x   = (const float*)d_in[0];  // [8192, 2048]
    const float* hdw = (const float*)d_in[1];  // [5, 2048, 2048]
    const float* W   = (const float*)d_in[2];  // [2048, 2048]
    const float* b   = (const float*)d_in[3];  // [2048]
    float* out = (float*)d_out;                // [8192, 2048]

    cudaFuncSetAttribute(gemm_mma_kernel, cudaFuncAttributeMaxDynamicSharedMemorySize, GEMM_SMEM);

    conv_a_kernel<<<(BATCH * IN_DIM / 4) / 256, 256>>>(x);
    conv_w_kernel<<<dim3(OUT_DIM / 32, IN_DIM / 32), dim3(32, 8)>>>(W);
    hd_bias_kernel<<<OUT_DIM / 256, 256>>>(hdw, b);

    dim3 grid(OUT_DIM / 128, BATCH / 128);     // (16, 64) = 1024 CTAs
    gemm_mma_kernel<<<grid, 256, GEMM_SMEM>>>(out);
}